// round 2
// baseline (speedup 1.0000x reference)
#include <cuda_runtime.h>
#include <math.h>

// X[32768,4096] fp32, W[64,4096] fp32, b[64] fp32, top_k=2
#define D_MODEL   4096
#define N_EXPERTS 64
#define TM        128   // tokens per CTA
#define BK        32    // K tile
#define NTHREADS  256

union SmemT {
    struct {
        float Xs[BK][TM + 1];          // stride 129 -> conflict-free transpose store
        float Ws[BK][N_EXPERTS + 1];   // stride 65
    } g;
    float scores[TM][N_EXPERTS + 1];   // stride 65
};

__global__ __launch_bounds__(NTHREADS, 2)
void topk_router_kernel(const float* __restrict__ X,
                        const float* __restrict__ W,
                        const float* __restrict__ b,
                        float* __restrict__ out,
                        int n_tokens)
{
    __shared__ SmemT sm;

    const int tid  = threadIdx.x;
    const int row0 = blockIdx.x * TM;

    const int ty = tid >> 4;   // 0..15 : token group (8 tokens each)
    const int tx = tid & 15;   // 0..15 : expert group (4 experts each)

    // Kahan-compensated accumulators across K-tiles
    float sum[8][4], cmp[8][4];
    #pragma unroll
    for (int i = 0; i < 8; i++)
        #pragma unroll
        for (int j = 0; j < 4; j++) { sum[i][j] = 0.0f; cmp[i][j] = 0.0f; }

    const float* Xblk = X + (size_t)row0 * D_MODEL;

    for (int kb = 0; kb < D_MODEL; kb += BK) {
        // ---- load X tile: 128 rows x 32 cols = 1024 float4, 4 per thread ----
        #pragma unroll
        for (int i = 0; i < 4; i++) {
            int idx = tid + i * NTHREADS;
            int r   = idx >> 3;     // 0..127
            int c4  = idx & 7;      // 0..7  (float4 column)
            float4 v = *(const float4*)(Xblk + (size_t)r * D_MODEL + kb + c4 * 4);
            sm.g.Xs[c4 * 4 + 0][r] = v.x;
            sm.g.Xs[c4 * 4 + 1][r] = v.y;
            sm.g.Xs[c4 * 4 + 2][r] = v.z;
            sm.g.Xs[c4 * 4 + 3][r] = v.w;
        }
        // ---- load W tile: 64 rows x 32 cols = 512 float4, 2 per thread ----
        #pragma unroll
        for (int i = 0; i < 2; i++) {
            int idx = tid + i * NTHREADS;
            int r   = idx >> 3;     // 0..63 (expert)
            int c4  = idx & 7;
            float4 v = *(const float4*)(W + (size_t)r * D_MODEL + kb + c4 * 4);
            sm.g.Ws[c4 * 4 + 0][r] = v.x;
            sm.g.Ws[c4 * 4 + 1][r] = v.y;
            sm.g.Ws[c4 * 4 + 2][r] = v.z;
            sm.g.Ws[c4 * 4 + 3][r] = v.w;
        }
        __syncthreads();

        // ---- per-tile local accumulation (plain FFMA) ----
        float tac[8][4];
        #pragma unroll
        for (int i = 0; i < 8; i++)
            #pragma unroll
            for (int j = 0; j < 4; j++) tac[i][j] = 0.0f;

        #pragma unroll
        for (int k = 0; k < BK; k++) {
            float xv[8], wv[4];
            #pragma unroll
            for (int i = 0; i < 8; i++) xv[i] = sm.g.Xs[k][ty * 8 + i];
            #pragma unroll
            for (int j = 0; j < 4; j++) wv[j] = sm.g.Ws[k][tx * 4 + j];
            #pragma unroll
            for (int i = 0; i < 8; i++)
                #pragma unroll
                for (int j = 0; j < 4; j++)
                    tac[i][j] = fmaf(xv[i], wv[j], tac[i][j]);
        }
        __syncthreads();

        // ---- Kahan merge of tile sum into running total ----
        // __fadd_rn/__fsub_rn: not contractible / not reassociable
        #pragma unroll
        for (int i = 0; i < 8; i++)
            #pragma unroll
            for (int j = 0; j < 4; j++) {
                float y = __fsub_rn(tac[i][j], cmp[i][j]);
                float t = __fadd_rn(sum[i][j], y);
                cmp[i][j] = __fsub_rn(__fsub_rn(t, sum[i][j]), y);
                sum[i][j] = t;
            }
    }

    // ---- scores (+bias, + residual compensation) to smem ----
    float bv[4];
    #pragma unroll
    for (int j = 0; j < 4; j++) bv[j] = b[tx * 4 + j];

    #pragma unroll
    for (int i = 0; i < 8; i++)
        #pragma unroll
        for (int j = 0; j < 4; j++) {
            float s = __fadd_rn(sum[i][j], __fsub_rn(0.0f, cmp[i][j]));
            sm.scores[ty * 8 + i][tx * 4 + j] = __fadd_rn(s, bv[j]);
        }

    __syncthreads();

    // ---- top-2 + softmax + write: one thread per token ----
    if (tid < TM) {
        int token = row0 + tid;
        float m1 = -INFINITY, m2 = -INFINITY;
        int   i1 = 0,         i2 = 0;
        #pragma unroll
        for (int e = 0; e < N_EXPERTS; e++) {
            float s = sm.scores[tid][e];
            if (s > m1) { m2 = m1; i2 = i1; m1 = s; i1 = e; }
            else if (s > m2) { m2 = s; i2 = e; }
        }
        float e2 = expf(m2 - m1);
        float inv = 1.0f / (1.0f + e2);
        float p1 = inv;
        float p2 = e2 * inv;

        out[(size_t)token * 2 + 0] = p1;
        out[(size_t)token * 2 + 1] = p2;
        size_t idx_base = (size_t)n_tokens * 2;
        out[idx_base + (size_t)token * 2 + 0] = (float)i1;
        out[idx_base + (size_t)token * 2 + 1] = (float)i2;
    }
}

extern "C" void kernel_launch(void* const* d_in, const int* in_sizes, int n_in,
                              void* d_out, int out_size)
{
    const float* X = (const float*)d_in[0];   // [N, 4096]
    const float* W = (const float*)d_in[1];   // [64, 4096]
    const float* b = (const float*)d_in[2];   // [64]
    float* out = (float*)d_out;

    int n_tokens = in_sizes[0] / D_MODEL;     // 32768
    int grid = n_tokens / TM;                 // 256 CTAs

    topk_router_kernel<<<grid, NTHREADS>>>(X, W, b, out, n_tokens);
}

// round 3
// speedup vs baseline: 1.0410x; 1.0410x over previous
#include <cuda_runtime.h>
#include <math.h>

// X[32768,4096] fp32, W[64,4096] fp32, b[64] fp32, top_k=2
#define D_MODEL   4096
#define N_EXPERTS 64
#define TM        128   // tokens per CTA
#define BK        32    // K tile
#define NTHREADS  256
#define XSTRIDE   36    // 32 + 4 pad floats; 9 granules (odd) -> conflict-free LDS.128
#define WSTRIDE   36

// dynamic smem layout (bytes):
//   Xs: [2][TM][XSTRIDE]  = 2*128*36*4 = 36864
//   Ws: [2][64][WSTRIDE]  = 2*64*36*4  = 18432
//   scores alias at base:  [128][65]*4 = 33280
#define XS_FLOATS (2 * TM * XSTRIDE)
#define WS_FLOATS (2 * N_EXPERTS * WSTRIDE)
#define SMEM_BYTES ((XS_FLOATS + WS_FLOATS) * 4)

__device__ __forceinline__ void cp16(float* s, const float* g) {
    unsigned sa = (unsigned)__cvta_generic_to_shared(s);
    asm volatile("cp.async.cg.shared.global [%0], [%1], 16;\n" :: "r"(sa), "l"(g));
}
__device__ __forceinline__ void cp_commit() {
    asm volatile("cp.async.commit_group;\n");
}
__device__ __forceinline__ void cp_wait0() {
    asm volatile("cp.async.wait_group 0;\n");
}

__global__ __launch_bounds__(NTHREADS, 2)
void topk_router_kernel(const float* __restrict__ X,
                        const float* __restrict__ W,
                        const float* __restrict__ b,
                        float* __restrict__ out,
                        int n_tokens)
{
    extern __shared__ float smem[];
    float* Xs = smem;                 // [2][TM][XSTRIDE]
    float* Ws = smem + XS_FLOATS;     // [2][64][WSTRIDE]
    float* scores = smem;             // [128][65], used after GEMM only

    const int tid  = threadIdx.x;
    const int row0 = blockIdx.x * TM;
    const int ty = tid >> 4;          // 0..15 : token group (8 tokens)
    const int tx = tid & 15;          // 0..15 : experts tx, tx+16, tx+32, tx+48

    // cp.async tile fetch: X 1024 float4 (4/thread), W 256 float4 (1/thread... 2/thread)
    const float* Xblk = X + (size_t)row0 * D_MODEL;
    const int xr  = tid >> 3;         // 0..31 base row per chunk step below
    const int xc4 = tid & 7;

    auto prefetch = [&](int kb, int bf) {
        float* Xb = Xs + bf * (TM * XSTRIDE);
        float* Wb = Ws + bf * (N_EXPERTS * WSTRIDE);
        #pragma unroll
        for (int i = 0; i < 4; i++) {
            int r = xr + i * 32;                         // 0..127
            cp16(Xb + r * XSTRIDE + xc4 * 4,
                 Xblk + (size_t)r * D_MODEL + kb + xc4 * 4);
        }
        #pragma unroll
        for (int i = 0; i < 2; i++) {
            int idx = tid + i * NTHREADS;
            int e   = idx >> 3;                          // 0..63
            int c4  = idx & 7;
            cp16(Wb + e * WSTRIDE + c4 * 4,
                 W + (size_t)e * D_MODEL + kb + c4 * 4);
        }
        cp_commit();
    };

    // Kahan-compensated accumulators across K-tiles
    float sum[8][4], cmp[8][4];
    #pragma unroll
    for (int i = 0; i < 8; i++)
        #pragma unroll
        for (int j = 0; j < 4; j++) { sum[i][j] = 0.0f; cmp[i][j] = 0.0f; }

    prefetch(0, 0);
    cp_wait0();
    __syncthreads();

    int buf = 0;
    for (int t = 0; t < D_MODEL / BK; t++) {
        if (t < D_MODEL / BK - 1)
            prefetch((t + 1) * BK, buf ^ 1);

        // ---- compute on buf ----
        const float* Xb = Xs + buf * (TM * XSTRIDE) + (ty * 8) * XSTRIDE;
        const float* Wb = Ws + buf * (N_EXPERTS * WSTRIDE) + tx * WSTRIDE;

        float tac[8][4];
        #pragma unroll
        for (int i = 0; i < 8; i++)
            #pragma unroll
            for (int j = 0; j < 4; j++) tac[i][j] = 0.0f;

        #pragma unroll
        for (int k4 = 0; k4 < BK / 4; k4++) {
            float4 wq[4];
            #pragma unroll
            for (int j = 0; j < 4; j++)
                wq[j] = *(const float4*)(Wb + (16 * j) * WSTRIDE + k4 * 4);
            #pragma unroll
            for (int i = 0; i < 8; i++) {
                float4 xq = *(const float4*)(Xb + i * XSTRIDE + k4 * 4);
                #pragma unroll
                for (int j = 0; j < 4; j++) {
                    tac[i][j] = fmaf(xq.x, wq[j].x, tac[i][j]);
                    tac[i][j] = fmaf(xq.y, wq[j].y, tac[i][j]);
                    tac[i][j] = fmaf(xq.z, wq[j].z, tac[i][j]);
                    tac[i][j] = fmaf(xq.w, wq[j].w, tac[i][j]);
                }
            }
        }

        // ---- Kahan merge (rn intrinsics: no contraction/reassociation) ----
        #pragma unroll
        for (int i = 0; i < 8; i++)
            #pragma unroll
            for (int j = 0; j < 4; j++) {
                float y = __fsub_rn(tac[i][j], cmp[i][j]);
                float s = __fadd_rn(sum[i][j], y);
                cmp[i][j] = __fsub_rn(__fsub_rn(s, sum[i][j]), y);
                sum[i][j] = s;
            }

        cp_wait0();          // next tile landed (this thread's part)
        __syncthreads();     // everyone done reading buf + all cp.async visible
        buf ^= 1;
    }

    // ---- scores (+bias, + residual compensation) to smem ----
    __syncthreads();   // scores alias the tile buffers
    float bv[4];
    #pragma unroll
    for (int j = 0; j < 4; j++) bv[j] = b[tx + 16 * j];

    #pragma unroll
    for (int i = 0; i < 8; i++)
        #pragma unroll
        for (int j = 0; j < 4; j++) {
            float s = __fadd_rn(sum[i][j], __fsub_rn(0.0f, cmp[i][j]));
            scores[(ty * 8 + i) * 65 + tx + 16 * j] = __fadd_rn(s, bv[j]);
        }

    __syncthreads();

    // ---- top-2 + softmax + write: one thread per token ----
    if (tid < TM) {
        int token = row0 + tid;
        float m1 = -INFINITY, m2 = -INFINITY;
        int   i1 = 0,         i2 = 0;
        #pragma unroll
        for (int e = 0; e < N_EXPERTS; e++) {
            float s = scores[tid * 65 + e];
            if (s > m1) { m2 = m1; i2 = i1; m1 = s; i1 = e; }
            else if (s > m2) { m2 = s; i2 = e; }
        }
        float e2 = expf(m2 - m1);
        float inv = 1.0f / (1.0f + e2);

        out[(size_t)token * 2 + 0] = inv;
        out[(size_t)token * 2 + 1] = e2 * inv;
        size_t idx_base = (size_t)n_tokens * 2;
        out[idx_base + (size_t)token * 2 + 0] = (float)i1;
        out[idx_base + (size_t)token * 2 + 1] = (float)i2;
    }
}

extern "C" void kernel_launch(void* const* d_in, const int* in_sizes, int n_in,
                              void* d_out, int out_size)
{
    const float* X = (const float*)d_in[0];   // [N, 4096]
    const float* W = (const float*)d_in[1];   // [64, 4096]
    const float* b = (const float*)d_in[2];   // [64]
    float* out = (float*)d_out;

    int n_tokens = in_sizes[0] / D_MODEL;     // 32768
    int grid = n_tokens / TM;                 // 256 CTAs

    cudaFuncSetAttribute(topk_router_kernel,
                         cudaFuncAttributeMaxDynamicSharedMemorySize, SMEM_BYTES);
    topk_router_kernel<<<grid, NTHREADS, SMEM_BYTES>>>(X, W, b, out, n_tokens);
}